// round 2
// baseline (speedup 1.0000x reference)
#include <cuda_runtime.h>
#include <cstdint>

#define B_DIM 16
#define L_DIM 2048
#define F_DIM 512

#define CTA_M 128
#define CTA_N 256
#define KC    32
#define NCH   (L_DIM / KC)   /* 64 */
#define THREADS 256

#define AS_STRIDE 36                     /* floats per A row (pad 32->36, conflict-free) */
#define BS_STRIDE 264                    /* floats per B row (pad 256->264, conflict-free) */
#define AS_FLOATS (CTA_M * AS_STRIDE)    /* 4608  */
#define BS_FLOATS (KC * BS_STRIDE)       /* 8448  */
#define SMEM_FLOATS (2 * AS_FLOATS + 2 * BS_FLOATS + 128)
#define SMEM_BYTES  (SMEM_FLOATS * 4)    /* 104960 */

__device__ __forceinline__ uint32_t f2tf32(float f) {
    uint32_t o;
    asm("cvt.rna.tf32.f32 %0, %1;" : "=r"(o) : "f"(f));
    return o;
}

__device__ __forceinline__ void mma_tf32(float* c, const uint32_t* a, const uint32_t* b) {
    asm volatile(
        "mma.sync.aligned.m16n8k8.row.col.f32.tf32.tf32.f32 "
        "{%0,%1,%2,%3}, {%4,%5,%6,%7}, {%8,%9}, {%0,%1,%2,%3};"
        : "+f"(c[0]), "+f"(c[1]), "+f"(c[2]), "+f"(c[3])
        : "r"(a[0]), "r"(a[1]), "r"(a[2]), "r"(a[3]), "r"(b[0]), "r"(b[1]));
}

__global__ void __launch_bounds__(THREADS, 1)
FrameAugment_39771397161402_kernel(const float* __restrict__ feature,
                                   const float* __restrict__ noise,
                                   float* __restrict__ out)
{
    extern __shared__ float sm[];
    float* As = sm;                                   /* [2][128][36] tf32 bits   */
    float* Bs = sm + 2 * AS_FLOATS;                   /* [2][32][264] tf32 bits   */
    float* Rs = sm + 2 * AS_FLOATS + 2 * BS_FLOATS;   /* [128] row sums           */

    const int tid  = threadIdx.x;
    const int w    = tid >> 5;
    const int lane = tid & 31;
    const int q    = lane >> 2;     /* 0..7 */
    const int qt   = lane & 3;      /* 0..3 */
    const int wm   = w >> 2;        /* 0..1 */
    const int wn   = w & 3;         /* 0..3 */

    const int b  = blockIdx.z;
    const int m0 = blockIdx.x * CTA_M;
    const int n0 = blockIdx.y * CTA_N;

    const float* nptr = noise   + ((size_t)b * L_DIM + m0) * L_DIM;
    const float* fptr = feature + (size_t)b * L_DIM * F_DIM + n0;
    float*       optr = out     + ((size_t)b * L_DIM + m0) * F_DIM + n0;

    float c[4][8][4];
    #pragma unroll
    for (int f = 0; f < 4; ++f)
        #pragma unroll
        for (int g = 0; g < 8; ++g)
            #pragma unroll
            for (int k = 0; k < 4; ++k) c[f][g][k] = 0.0f;

    float  rsum[4] = {0.f, 0.f, 0.f, 0.f};
    float4 stA[4];
    float4 stB[8];

    /* ---------------- helpers expanded inline via macros ---------------- */
#define LOAD_A(IT)                                                              \
    {                                                                           \
        _Pragma("unroll")                                                       \
        for (int qq = 0; qq < 4; ++qq) {                                        \
            const int v = tid + 256 * qq;                                       \
            const int row = v >> 3, c4 = v & 7;                                 \
            stA[qq] = *(const float4*)(nptr + (size_t)row * L_DIM + (IT) * KC + c4 * 4); \
        }                                                                       \
    }

#define COMMIT_A(BUF)                                                           \
    {                                                                           \
        _Pragma("unroll")                                                       \
        for (int qq = 0; qq < 4; ++qq) {                                        \
            const int v = tid + 256 * qq;                                       \
            const int row = v >> 3, c4 = v & 7;                                 \
            const float e0 = __expf(stA[qq].x), e1 = __expf(stA[qq].y);         \
            const float e2 = __expf(stA[qq].z), e3 = __expf(stA[qq].w);         \
            float s = (e0 + e1) + (e2 + e3);                                    \
            s += __shfl_xor_sync(0xFFFFFFFFu, s, 1);                            \
            s += __shfl_xor_sync(0xFFFFFFFFu, s, 2);                            \
            s += __shfl_xor_sync(0xFFFFFFFFu, s, 4);                            \
            rsum[qq] += s;                                                      \
            uint4 u;                                                            \
            u.x = f2tf32(e0); u.y = f2tf32(e1); u.z = f2tf32(e2); u.w = f2tf32(e3); \
            *(uint4*)(As + (BUF) * AS_FLOATS + row * AS_STRIDE + c4 * 4) = u;   \
        }                                                                       \
    }

#define LOAD_B(IT)                                                              \
    {                                                                           \
        _Pragma("unroll")                                                       \
        for (int i = 0; i < 8; ++i) {                                           \
            const int u = tid + 256 * i;                                        \
            const int r = u >> 6, cb = u & 63;                                  \
            stB[i] = *(const float4*)(fptr + (size_t)((IT) * KC + r) * F_DIM + cb * 4); \
        }                                                                       \
    }

#define COMMIT_B(BUF)                                                           \
    {                                                                           \
        _Pragma("unroll")                                                       \
        for (int i = 0; i < 8; ++i) {                                           \
            const int u = tid + 256 * i;                                        \
            const int r = u >> 6, cb = u & 63;                                  \
            uint4 t;                                                            \
            t.x = f2tf32(stB[i].x); t.y = f2tf32(stB[i].y);                     \
            t.z = f2tf32(stB[i].z); t.w = f2tf32(stB[i].w);                     \
            *(uint4*)(Bs + (BUF) * BS_FLOATS + r * BS_STRIDE + cb * 4) = t;     \
        }                                                                       \
    }

    /* ---------------- prologue: fill buffer 0 ---------------- */
    LOAD_A(0);
    LOAD_B(0);
    COMMIT_A(0);
    COMMIT_B(0);
    __syncthreads();

    /* ---------------- main pipelined loop ---------------- */
    for (int it = 0; it < NCH; ++it) {
        const int cur = it & 1;

        if (it + 1 < NCH) {
            LOAD_A(it + 1);
            LOAD_B(it + 1);
        }

        /* MMA over current buffer */
        {
            const uint32_t* Ab = (const uint32_t*)(As + cur * AS_FLOATS);
            const uint32_t* Bb = (const uint32_t*)(Bs + cur * BS_FLOATS);
            #pragma unroll
            for (int ks = 0; ks < 4; ++ks) {
                uint32_t a[4][4];
                #pragma unroll
                for (int f = 0; f < 4; ++f) {
                    const int ar = wm * 64 + f * 16 + q;
                    const int ak = ks * 8 + qt;
                    a[f][0] = Ab[ar * AS_STRIDE + ak];
                    a[f][1] = Ab[(ar + 8) * AS_STRIDE + ak];
                    a[f][2] = Ab[ar * AS_STRIDE + ak + 4];
                    a[f][3] = Ab[(ar + 8) * AS_STRIDE + ak + 4];
                }
                uint32_t bb[8][2];
                #pragma unroll
                for (int g = 0; g < 8; ++g) {
                    const int bc = wn * 64 + g * 8 + q;
                    bb[g][0] = Bb[(ks * 8 + qt) * BS_STRIDE + bc];
                    bb[g][1] = Bb[(ks * 8 + qt + 4) * BS_STRIDE + bc];
                }
                #pragma unroll
                for (int f = 0; f < 4; ++f)
                    #pragma unroll
                    for (int g = 0; g < 8; ++g)
                        mma_tf32(c[f][g], a[f], bb[g]);
            }
        }

        if (it + 1 < NCH) {
            const int nxt = (it + 1) & 1;
            COMMIT_A(nxt);
            COMMIT_B(nxt);
        }
        __syncthreads();
    }

    /* ---------------- row sums -> smem ---------------- */
    if ((tid & 7) == 0) {
        #pragma unroll
        for (int qq = 0; qq < 4; ++qq)
            Rs[(tid >> 3) + 32 * qq] = rsum[qq];
    }
    __syncthreads();

    /* ---------------- epilogue: divide + store ---------------- */
    #pragma unroll
    for (int f = 0; f < 4; ++f) {
        const int r0 = wm * 64 + f * 16 + q;
        const int r1 = r0 + 8;
        const float inv0 = 1.0f / Rs[r0];
        const float inv1 = 1.0f / Rs[r1];
        #pragma unroll
        for (int g = 0; g < 8; ++g) {
            const int col = wn * 64 + g * 8 + 2 * qt;
            float2 lo, hi;
            lo.x = c[f][g][0] * inv0;
            lo.y = c[f][g][1] * inv0;
            hi.x = c[f][g][2] * inv1;
            hi.y = c[f][g][3] * inv1;
            *(float2*)(optr + (size_t)r0 * F_DIM + col) = lo;
            *(float2*)(optr + (size_t)r1 * F_DIM + col) = hi;
        }
    }
}

extern "C" void kernel_launch(void* const* d_in, const int* in_sizes, int n_in,
                              void* d_out, int out_size) {
    (void)in_sizes; (void)n_in; (void)out_size;
    const float* feature = (const float*)d_in[0];
    const float* noise   = (const float*)d_in[1];
    float* out = (float*)d_out;

    cudaFuncSetAttribute(FrameAugment_39771397161402_kernel,
                         cudaFuncAttributeMaxDynamicSharedMemorySize, SMEM_BYTES);

    dim3 grid(L_DIM / CTA_M, F_DIM / CTA_N, B_DIM);   /* 16 x 2 x 16 = 512 CTAs */
    FrameAugment_39771397161402_kernel<<<grid, THREADS, SMEM_BYTES>>>(feature, noise, out);
}